// round 16
// baseline (speedup 1.0000x reference)
#include <cuda_runtime.h>
#include <cuda_fp16.h>
#include <math.h>

typedef unsigned int u32;
typedef unsigned long long u64;

enum { EP_RELU = 0, EP_PLAIN = 1, EP_ADD = 2, EP_GATE = 3, EP_OUT = 4, EP_PART = 5, EP_MULG = 6 };

// ---------------- device scratch (allocation-free) ----------------
__device__ float g_xv[64 * 64 * 64 * 64];   // x voxel-major [v][64]
__device__ float g_hv[64 * 64 * 64 * 32];   // hx voxel-major (scaled 0.5)
__device__ float g_y [32 * 32 * 32 * 64];
__device__ float g_t [32 * 32 * 32 * 64];
__device__ float g_cA[32 * 32 * 32 * 64];
__device__ float g_cB[16 * 16 * 16 * 64];
__device__ float g_part[8 * 1024 * 1024];
// packed weights: per (tap, chunk16) two blobs (hi, lo) of cout*16 halves in
// exact mma.sync B-fragment order
__device__ __half g_wh  [8  * 2 * 2 * 64 * 16];
__device__ __half g_wc0 [8  * 4 * 2 * 64 * 16];
__device__ __half g_wr0 [27 * 4 * 2 * 64 * 16];
__device__ __half g_wr1 [27 * 4 * 2 * 64 * 16];
__device__ __half g_wc1 [27 * 4 * 2 * 64 * 16];
__device__ __half g_wout[27 * 4 * 2 * 32 * 16];

// ---------------- helpers ----------------
__device__ __forceinline__ u32 s2u(const void* p) {
    u32 a;
    asm("{ .reg .u64 t; cvta.to.shared.u64 t, %1; cvt.u32.u64 %0, t; }" : "=r"(a) : "l"(p));
    return a;
}
__device__ __forceinline__ u32 p2(float a, float b) {
    __half2 h = __halves2half2(__float2half_rn(a), __float2half_rn(b));
    return *reinterpret_cast<u32*>(&h);
}
__device__ __forceinline__ void ldm4(u32* r, u32 addr) {
    asm volatile("ldmatrix.sync.aligned.m8n8.x4.shared.b16 {%0,%1,%2,%3}, [%4];"
                 : "=r"(r[0]), "=r"(r[1]), "=r"(r[2]), "=r"(r[3]) : "r"(addr));
}
__device__ __forceinline__ void mma16816(float* c, const u32* a, uint2 b) {
    asm volatile(
        "mma.sync.aligned.m16n8k16.row.col.f32.f16.f16.f32 "
        "{%0,%1,%2,%3}, {%4,%5,%6,%7}, {%8,%9}, {%0,%1,%2,%3};"
        : "+f"(c[0]), "+f"(c[1]), "+f"(c[2]), "+f"(c[3])
        : "r"(a[0]), "r"(a[1]), "r"(a[2]), "r"(a[3]), "r"(b.x), "r"(b.y));
}
__device__ __forceinline__ float gatef(float a) {
    float s = 2.f * a;  // undo hx 0.5 pre-scale
    return (s > 0.f) ? 1.f / (1.f + expf(-s)) : 0.5f;
}

// ---------------- relayout x: NCDHW -> voxel-major [v][64] ----------------
__global__ void relayoutk(const float* __restrict__ in, float* __restrict__ outv, int d3) {
    __shared__ float s[64][33];
    int v0 = blockIdx.x * 32;
    int t = threadIdx.x;
    int vl = t & 31;
#pragma unroll
    for (int k = 0; k < 8; ++k) {
        int c = (t >> 5) + 8 * k;
        s[c][vl] = in[(size_t)c * d3 + v0 + vl];
    }
    __syncthreads();
    int vloc = t >> 3;
#pragma unroll
    for (int k = 0; k < 2; ++k) {
        int f4 = (t & 7) * 2 + k;
        float4 w = make_float4(s[f4 * 4 + 0][vloc], s[f4 * 4 + 1][vloc],
                               s[f4 * 4 + 2][vloc], s[f4 * 4 + 3][vloc]);
        *(float4*)(outv + (size_t)(v0 + vloc) * 64 + f4 * 4) = w;
    }
}

// ---------------- pack ONE weight tensor region into B-fragment layout ----------------
__device__ __forceinline__ void packone(const float* __restrict__ w, __half* __restrict__ wp,
                                        int i, int cout, int cin, int taps) {
    int co = i / (cin * taps);
    int r = i % (cin * taps);
    int ci = r / taps;
    int t = r % taps;
    float v = w[i];
    float hi = __half2float(__float2half_rn(v));
    float lo = v - hi;
    int nch = cin >> 4;
    int q = ci >> 4, kk = ci & 15;
    int nf = co >> 3, nn = co & 7;
    int l = (nn << 2) + ((kk & 7) >> 1);
    int rr = kk >> 3, h = kk & 1;
    size_t base = (size_t)((t * nch + q) * 2) * (size_t)(cout * 16);
    size_t off = (size_t)nf * 128 + l * 4 + rr * 2 + h;
    wp[base + off] = __float2half_rn(hi);
    wp[base + cout * 16 + off] = __float2half_rn(lo);
}

__global__ void packall(const float* wh_, const float* wc0_, const float* wr0_,
                        const float* wr1_, const float* wc1_, const float* wout_,
                        __half* ph, __half* pc0, __half* pr0, __half* pr1,
                        __half* pc1, __half* pout) {
    int i = blockIdx.x * 256 + threadIdx.x;
    const int n0 = 64 * 32 * 8;
    const int n1 = n0 + 64 * 64 * 8;
    const int n2 = n1 + 64 * 64 * 27;
    const int n3 = n2 + 64 * 64 * 27;
    const int n4 = n3 + 64 * 64 * 27;
    const int n5 = n4 + 32 * 64 * 27;
    if (i < n0)      packone(wh_,  ph,  i,      64, 32, 8);
    else if (i < n1) packone(wc0_, pc0, i - n0, 64, 64, 8);
    else if (i < n2) packone(wr0_, pr0, i - n1, 64, 64, 27);
    else if (i < n3) packone(wr1_, pr1, i - n2, 64, 64, 27);
    else if (i < n4) packone(wc1_, pc1, i - n3, 64, 64, 27);
    else if (i < n5) packone(wout_, pout, i - n4, 32, 64, 27);
}

// ---------------- tensor-core implicit conv body (2-pass: A fp16, B hi/lo) ----------------
// CTA: 256 thr = 8 warps; tile 8x4x4 = 128 voxels.
// Warp w: m-rows [32*(w&3), +32), N-half (w>>2).
// KSZ=3: register-prefetch double-buffered halo pipeline.
// MMA order: all bh passes across nf, then all bl passes -> long acc reuse distance.
template<int KSZ, int N_, int MODE>
__device__ __forceinline__ void conv_body(
        int bt_in, int sp,
        const float* __restrict__ in, const __half* __restrict__ wp,
        float* __restrict__ out0, float* __restrict__ out1,
        int d, int cin, int taps, int nsplit, int d3) {
    constexpr int NF = N_ / 8;
    constexpr int NFH = NF / 2;
    constexpr int HN = 360;                  // halo rows (10*6*6) for 8x4x4 tile
    __shared__ __align__(16) __half ah[2][(KSZ == 3) ? HN * 16 : 8];

    const int tid = threadIdx.x, w = tid >> 5, lane = tid & 31;
    const int wm = w & 3, half_ = w >> 2;
    const int ntx = d >> 3, nty = d >> 2;
    int bt = bt_in;
    const int x0 = (bt % ntx) << 3;
    bt /= ntx;
    const int y0 = (bt % nty) << 2;
    const int z0 = (bt / nty) << 2;
    const int tpp = taps / nsplit;
    const int tap0 = sp * tpp;
    const int nch = cin >> 4;
    const int din = (KSZ == 2) ? 2 * d : d;

    float acc[2][NFH][4];
#pragma unroll
    for (int mf = 0; mf < 2; ++mf)
#pragma unroll
        for (int nf = 0; nf < NFH; ++nf)
#pragma unroll
            for (int k = 0; k < 4; ++k) acc[mf][nf][k] = 0.f;

    float4 pf[6];  // prefetch regs: ceil(1440/256)=6 per thread

    auto LOADQ = [&](int q) {
        int k = 0;
#pragma unroll
        for (int i = tid; i < HN * 4; i += 256, ++k) {
            int row = i >> 2, c4 = i & 3;
            int hx = row % 10, r2 = row / 10, hy = r2 % 6, hz = r2 / 6;
            int gx = x0 + hx - 1, gy = y0 + hy - 1, gz = z0 + hz - 1;
            float4 v = make_float4(0.f, 0.f, 0.f, 0.f);
            if ((unsigned)gx < (unsigned)d && (unsigned)gy < (unsigned)d &&
                (unsigned)gz < (unsigned)d)
                v = *(const float4*)(in + ((size_t)(gz * d + gy) * d + gx) * cin
                                     + (q << 4) + (c4 << 2));
            pf[k] = v;
        }
    };
    auto STOREQ = [&](int b) {
        int k = 0;
#pragma unroll
        for (int i = tid; i < HN * 4; i += 256, ++k) {
            int row = i >> 2, c4 = i & 3;
            float4 v = pf[k];
            uint2 hh;
            hh.x = p2(v.x, v.y); hh.y = p2(v.z, v.w);
            *(uint2*)(ah[b] + row * 16 + c4 * 4) = hh;
        }
    };

    if (KSZ == 3) {
        LOADQ(0);
        STOREQ(0);
        __syncthreads();
    }

    for (int q = 0; q < nch; ++q) {
        const int b = q & 1;
        if (KSZ == 3 && q + 1 < nch) LOADQ(q + 1);   // overlap with compute below

        const u32 ahb = s2u(ah[b]);

        for (int tt = 0; tt < tpp; ++tt) {
            const int tap = tap0 + tt;
            int dzz, dyy, dxx;
            if (KSZ == 3) { dzz = tap / 9; dyy = (tap / 3) % 3; dxx = tap % 3; }
            else          { dzz = tap >> 2; dyy = (tap >> 1) & 1; dxx = tap & 1; }

            // hoisted B-fragment loads for this tap
            const __half* bb = wp + (size_t)((tap * nch + q) * 2) * (N_ * 16);
            uint2 bhv[NFH], blv[NFH];
#pragma unroll
            for (int nf = 0; nf < NFH; ++nf) {
                const int nfg = half_ * NFH + nf;
                bhv[nf] = *(const uint2*)(bb + nfg * 128 + lane * 4);
                blv[nf] = *(const uint2*)(bb + N_ * 16 + nfg * 128 + lane * 4);
            }

            u32 AH[2][4];
            if (KSZ == 3) {
#pragma unroll
                for (int mf = 0; mf < 2; ++mf) {
                    int r = lane & 15;
                    int mg = (wm << 5) + (mf << 4) + r;
                    int lx = mg & 7, ly = (mg >> 3) & 3, lz = mg >> 5;
                    int rowi = ((lz + dzz) * 6 + ly + dyy) * 10 + lx + dxx;
                    u32 ao = (u32)rowi * 32 + ((lane >> 4) << 4);
                    ldm4(AH[mf], ahb + ao);
                }
            } else {
#pragma unroll
                for (int mf = 0; mf < 2; ++mf) {
                    int r = lane >> 2;
                    int cb = (q << 4) + ((lane & 3) << 1);
                    int mg0 = (wm << 5) + (mf << 4) + r;
                    int mg1 = mg0 + 8;
                    int lx0 = mg0 & 7, ly0 = (mg0 >> 3) & 3, lz0 = mg0 >> 5;
                    int lx1 = mg1 & 7, ly1 = (mg1 >> 3) & 3, lz1 = mg1 >> 5;
                    size_t v0 = ((size_t)(2 * (z0 + lz0) + dzz) * din
                                 + (2 * (y0 + ly0) + dyy)) * din + 2 * (x0 + lx0) + dxx;
                    size_t v1 = ((size_t)(2 * (z0 + lz1) + dzz) * din
                                 + (2 * (y0 + ly1) + dyy)) * din + 2 * (x0 + lx1) + dxx;
                    float2 e00 = *(const float2*)(in + v0 * cin + cb);
                    float2 e10 = *(const float2*)(in + v1 * cin + cb);
                    float2 e01 = *(const float2*)(in + v0 * cin + cb + 8);
                    float2 e11 = *(const float2*)(in + v1 * cin + cb + 8);
                    AH[mf][0] = p2(e00.x, e00.y);
                    AH[mf][1] = p2(e10.x, e10.y);
                    AH[mf][2] = p2(e01.x, e01.y);
                    AH[mf][3] = p2(e11.x, e11.y);
                }
            }

            // bh pass over all nf, then bl pass: acc reuse distance = 2*NFH MMAs
#pragma unroll
            for (int nf = 0; nf < NFH; ++nf) {
                mma16816(acc[0][nf], AH[0], bhv[nf]);
                mma16816(acc[1][nf], AH[1], bhv[nf]);
            }
#pragma unroll
            for (int nf = 0; nf < NFH; ++nf) {
                mma16816(acc[0][nf], AH[0], blv[nf]);
                mma16816(acc[1][nf], AH[1], blv[nf]);
            }
        }

        if (KSZ == 3 && q + 1 < nch) {
            STOREQ(b ^ 1);
            __syncthreads();
        }
    }

    // ---------------- epilogue ----------------
    const int rr = lane >> 2, cc = (lane & 3) << 1;
#pragma unroll
    for (int mf = 0; mf < 2; ++mf) {
        int mg0 = (wm << 5) + (mf << 4) + rr;
        int mg1 = mg0 + 8;
        int lx0 = mg0 & 7, ly0 = (mg0 >> 3) & 3, lz0 = mg0 >> 5;
        int lx1 = mg1 & 7, ly1 = (mg1 >> 3) & 3, lz1 = mg1 >> 5;
        size_t v0 = ((size_t)(z0 + lz0) * d + (y0 + ly0)) * d + (x0 + lx0);
        size_t v1 = ((size_t)(z0 + lz1) * d + (y0 + ly1)) * d + (x0 + lx1);
#pragma unroll
        for (int nf = 0; nf < NFH; ++nf) {
            const int nfg = half_ * NFH + nf;
            int c0 = (nfg << 3) + cc;
            float a0 = acc[mf][nf][0], a1 = acc[mf][nf][1];
            float a2 = acc[mf][nf][2], a3 = acc[mf][nf][3];
            if (MODE == EP_PART) {
                size_t slab = (size_t)sp * ((size_t)d * d * d * N_);
                *(float2*)(out0 + slab + v0 * N_ + c0) = make_float2(a0, a1);
                *(float2*)(out0 + slab + v1 * N_ + c0) = make_float2(a2, a3);
            } else if (MODE == EP_RELU || MODE == EP_PLAIN) {
                if (MODE == EP_RELU) {
                    a0 = fmaxf(a0, 0.f); a1 = fmaxf(a1, 0.f);
                    a2 = fmaxf(a2, 0.f); a3 = fmaxf(a3, 0.f);
                }
                *(float2*)(out0 + v0 * N_ + c0) = make_float2(a0, a1);
                *(float2*)(out0 + v1 * N_ + c0) = make_float2(a2, a3);
            } else if (MODE == EP_ADD) {
                float2 p0 = *(float2*)(out0 + v0 * N_ + c0);
                float2 p1 = *(float2*)(out0 + v1 * N_ + c0);
                p0.x += a0; p0.y += a1; p1.x += a2; p1.y += a3;
                *(float2*)(out0 + v0 * N_ + c0) = p0;
                *(float2*)(out0 + v1 * N_ + c0) = p1;
            } else if (MODE == EP_GATE) {
                float2 p0 = *(float2*)(out0 + v0 * N_ + c0);
                float2 p1 = *(float2*)(out0 + v1 * N_ + c0);
                p0.x *= gatef(a0); p0.y *= gatef(a1);
                p1.x *= gatef(a2); p1.y *= gatef(a3);
                *(float2*)(out0 + v0 * N_ + c0) = p0;
                *(float2*)(out0 + v1 * N_ + c0) = p1;
            } else if (MODE == EP_MULG) {
                float2 g0 = *(const float2*)(out1 + v0 * N_ + c0);
                float2 g1 = *(const float2*)(out1 + v1 * N_ + c0);
                *(float2*)(out0 + v0 * N_ + c0) =
                    make_float2(a0 * gatef(g0.x), a1 * gatef(g0.y));
                *(float2*)(out0 + v1 * N_ + c0) =
                    make_float2(a2 * gatef(g1.x), a3 * gatef(g1.y));
            } else {  // EP_OUT: channel-major 0.5x + voxel-major hx copy
                out0[(size_t)(c0 + 0) * d3 + v0] = 0.5f * a0;
                out0[(size_t)(c0 + 1) * d3 + v0] = 0.5f * a1;
                out0[(size_t)(c0 + 0) * d3 + v1] = 0.5f * a2;
                out0[(size_t)(c0 + 1) * d3 + v1] = 0.5f * a3;
                if (out1) {
                    *(float2*)(out1 + v0 * N_ + c0) = make_float2(0.5f * a0, 0.5f * a1);
                    *(float2*)(out1 + v1 * N_ + c0) = make_float2(0.5f * a2, 0.5f * a3);
                }
            }
        }
    }
}

template<int KSZ, int N_, int MODE>
__global__ __launch_bounds__(256, 2)
void convT(const float* __restrict__ in, const __half* __restrict__ wp,
           float* __restrict__ out0, float* __restrict__ out1,
           int d, int cin, int taps, int nsplit, int d3) {
    conv_body<KSZ, N_, MODE>(blockIdx.x, blockIdx.y, in, wp, out0, out1,
                             d, cin, taps, nsplit, d3);
}

// fused: conv_out@d64 (nA CTAs) + iter1 wc0@d32 (rest) — both read xv only
__global__ __launch_bounds__(256, 2)
void fused1(const float* __restrict__ xv, const __half* __restrict__ wo,
            float* __restrict__ out0, float* __restrict__ hv,
            const __half* __restrict__ wc0, float* __restrict__ bY, int nA) {
    if ((int)blockIdx.x < nA)
        conv_body<3, 32, EP_OUT>(blockIdx.x, 0, xv, wo, out0, hv,
                                 64, 64, 27, 1, 64 * 64 * 64);
    else
        conv_body<2, 64, EP_RELU>(blockIdx.x - nA, 0, xv, wc0, bY, 0,
                                  32, 64, 8, 1, 0);
}

// fused: conv_out@d32 (nA CTAs) + iter2 wc0 split (rest) — both read post-gate cA
__global__ __launch_bounds__(256, 2)
void fused2(const float* __restrict__ cA, const __half* __restrict__ wo,
            float* __restrict__ out1, float* __restrict__ hv,
            const __half* __restrict__ wc0, float* __restrict__ bP, int nA) {
    if ((int)blockIdx.x < nA)
        conv_body<3, 32, EP_OUT>(blockIdx.x, 0, cA, wo, out1, hv,
                                 32, 64, 27, 1, 32 * 32 * 32);
    else {
        int b2 = blockIdx.x - nA;          // 32 tiles x 4 splits
        conv_body<2, 64, EP_PART>(b2 & 31, b2 >> 5, cA, wc0, bP, 0,
                                  16, 64, 8, 4, 0);
    }
}

// fused: iter1 wr0 k3 (nA CTAs, bY->bT) + raw gate conv k2 (hv->bG), independent
__global__ __launch_bounds__(256, 2)
void fused3(const float* __restrict__ bY, const __half* __restrict__ wr0,
            float* __restrict__ bT,
            const float* __restrict__ hv, const __half* __restrict__ wh,
            float* __restrict__ bG, int nA) {
    if ((int)blockIdx.x < nA)
        conv_body<3, 64, EP_RELU>(blockIdx.x, 0, bY, wr0, bT, 0,
                                  32, 64, 27, 1, 0);
    else
        conv_body<2, 64, EP_PLAIN>(blockIdx.x - nA, 0, hv, wh, bG, 0,
                                   32, 32, 8, 1, 0);
}

// ---------------- split-K reduce (voxel-major) ----------------
template<int MODE>
__global__ void reduceT(const float* __restrict__ part, float* __restrict__ out0,
                        float* __restrict__ out1, int n, int slab, int nsplit,
                        int d3, int clog) {
    int i = blockIdx.x * 256 + threadIdx.x;
    if (i >= n) return;
    float s = 0.f;
    for (int k = 0; k < nsplit; ++k) s += part[(size_t)k * slab + i];
    if (MODE == EP_RELU) out0[i] = fmaxf(s, 0.f);
    else if (MODE == EP_PLAIN) out0[i] = s;
    else if (MODE == EP_ADD) out0[i] += s;
    else if (MODE == EP_GATE) out0[i] *= gatef(s);
    else {  // EP_OUT
        int c = i & ((1 << clog) - 1);
        int v = i >> clog;
        float h = 0.5f * s;
        out0[(size_t)c * d3 + v] = h;
        if (out1) out1[i] = h;
    }
}

// ---------------- driver ----------------
extern "C" void kernel_launch(void* const* d_in, const int* in_sizes, int n_in,
                              void* d_out, int out_size) {
    (void)in_sizes; (void)n_in; (void)out_size;
    const float* x     = (const float*)d_in[0];
    const float* w_h   = (const float*)d_in[1];
    const float* w_c0  = (const float*)d_in[2];
    const float* w_r0  = (const float*)d_in[3];
    const float* w_r1  = (const float*)d_in[4];
    const float* w_c1  = (const float*)d_in[5];
    const float* w_out = (const float*)d_in[6];
    float* out = (float*)d_out;

    float *xv, *hv, *bY, *bT, *cA, *cB, *bP;
    __half *wh, *wc0, *wr0, *wr1, *wc1, *wo;
    cudaGetSymbolAddress((void**)&xv, g_xv);
    cudaGetSymbolAddress((void**)&hv, g_hv);
    cudaGetSymbolAddress((void**)&bY, g_y);
    cudaGetSymbolAddress((void**)&bT, g_t);
    cudaGetSymbolAddress((void**)&cA, g_cA);
    cudaGetSymbolAddress((void**)&cB, g_cB);
    cudaGetSymbolAddress((void**)&bP, g_part);
    cudaGetSymbolAddress((void**)&wh, g_wh);
    cudaGetSymbolAddress((void**)&wc0, g_wc0);
    cudaGetSymbolAddress((void**)&wr0, g_wr0);
    cudaGetSymbolAddress((void**)&wr1, g_wr1);
    cudaGetSymbolAddress((void**)&wc1, g_wc1);
    cudaGetSymbolAddress((void**)&wo, g_wout);
    float* bPg = bP + 4 * 1024 * 1024;     // disjoint slab region for gate partials

    const int d3_64 = 262144, d3_32 = 32768, d3_16 = 4096, d3_8 = 512;

    relayoutk<<<d3_64 / 32, 256>>>(x, xv, d3_64);
    {
        const int ntot = 64 * 32 * 8 + 64 * 64 * 8 + 3 * 64 * 64 * 27 + 32 * 64 * 27;
        packall<<<(ntot + 255) / 256, 256>>>(w_h, w_c0, w_r0, w_r1, w_c1, w_out,
                                             wh, wc0, wr0, wr1, wc1, wo);
    }

    const size_t o0 = 0;
    const size_t o1 = o0 + (size_t)32 * d3_64;
    const size_t o2 = o1 + (size_t)32 * d3_32;
    const size_t o3 = o2 + (size_t)32 * d3_16;

    // fused: feas[0]=0.5*conv_out(x)@64 (+hv) || iter1 wc0 (both read xv only)
    fused1<<<2048 + 256, 256>>>(xv, wo, out + o0, hv, wc0, bY, 2048);

    // ---- iteration 1 chain: d=32 ----
    fused3<<<256 + 256, 256>>>(bY, wr0, bT, hv, wh, bP, 256);
    convT<3, 64, EP_ADD ><<<256, 256>>>(bT, wr1, bY, 0, 32, 64, 27, 1, 0);
    convT<3, 64, EP_MULG><<<256, 256>>>(bY, wc1, cA, bP, 32, 64, 27, 1, 0);

    // fused: conv_out@32 (out+o1, hv) || iter2 wc0 split (both read post-gate cA)
    fused2<<<256 + 128, 256>>>(cA, wo, out + o1, hv, wc0, bP, 256);

    // ---- iteration 2: d=16, tap-split ----
    {
        const int nv = d3_16, NB = nv / 128;
        convT<2, 64, EP_PART><<<dim3(NB, 4), 256>>>(hv, wh, bPg, 0, 16, 32, 8, 4, 0);
        reduceT<EP_RELU><<<(nv * 64 + 255) / 256, 256>>>(bP, bY, 0, nv * 64, nv * 64, 4, 0, 0);
        convT<3, 64, EP_PART><<<dim3(NB, 9), 256>>>(bY, wr0, bP, 0, 16, 64, 27, 9, 0);
        reduceT<EP_RELU><<<(nv * 64 + 255) / 256, 256>>>(bP, bT, 0, nv * 64, nv * 64, 9, 0, 0);
        convT<3, 64, EP_PART><<<dim3(NB, 9), 256>>>(bT, wr1, bP, 0, 16, 64, 27, 9, 0);
        reduceT<EP_ADD><<<(nv * 64 + 255) / 256, 256>>>(bP, bY, 0, nv * 64, nv * 64, 9, 0, 0);
        convT<3, 64, EP_PART><<<dim3(NB, 9), 256>>>(bY, wc1, bP, 0, 16, 64, 27, 9, 0);
        reduceT<EP_PLAIN><<<(nv * 64 + 255) / 256, 256>>>(bP, cB, 0, nv * 64, nv * 64, 9, 0, 0);
        reduceT<EP_GATE><<<(nv * 64 + 255) / 256, 256>>>(bPg, cB, 0, nv * 64, nv * 64, 4, 0, 0);
        convT<3, 32, EP_PART><<<dim3(NB, 9), 256>>>(cB, wo, bP, 0, 16, 64, 27, 9, 0);
        reduceT<EP_OUT><<<(nv * 32 + 255) / 256, 256>>>(bP, out + o2, hv, nv * 32, nv * 32, 9, d3_16, 5);
    }

    // ---- iteration 3: d=8, tap-split ----
    {
        const int nv = d3_8, NB = nv / 128;
        convT<2, 64, EP_PART><<<dim3(NB, 8), 256>>>(hv, wh, bPg, 0, 8, 32, 8, 8, 0);
        convT<2, 64, EP_PART><<<dim3(NB, 8), 256>>>(cB, wc0, bP, 0, 8, 64, 8, 8, 0);
        reduceT<EP_RELU><<<(nv * 64 + 255) / 256, 256>>>(bP, bY, 0, nv * 64, nv * 64, 8, 0, 0);
        convT<3, 64, EP_PART><<<dim3(NB, 27), 256>>>(bY, wr0, bP, 0, 8, 64, 27, 27, 0);
        reduceT<EP_RELU><<<(nv * 64 + 255) / 256, 256>>>(bP, bT, 0, nv * 64, nv * 64, 27, 0, 0);
        convT<3, 64, EP_PART><<<dim3(NB, 27), 256>>>(bT, wr1, bP, 0, 8, 64, 27, 27, 0);
        reduceT<EP_ADD><<<(nv * 64 + 255) / 256, 256>>>(bP, bY, 0, nv * 64, nv * 64, 27, 0, 0);
        convT<3, 64, EP_PART><<<dim3(NB, 27), 256>>>(bY, wc1, bP, 0, 8, 64, 27, 27, 0);
        reduceT<EP_PLAIN><<<(nv * 64 + 255) / 256, 256>>>(bP, cA, 0, nv * 64, nv * 64, 27, 0, 0);
        reduceT<EP_GATE><<<(nv * 64 + 255) / 256, 256>>>(bPg, cA, 0, nv * 64, nv * 64, 8, 0, 0);
        convT<3, 32, EP_PART><<<dim3(NB, 27), 256>>>(cA, wo, bP, 0, 8, 64, 27, 27, 0);
        reduceT<EP_OUT><<<(nv * 32 + 255) / 256, 256>>>(bP, out + o3, (float*)0, nv * 32, nv * 32, 27, d3_8, 5);
    }
}

// round 17
// speedup vs baseline: 1.0652x; 1.0652x over previous
#include <cuda_runtime.h>
#include <cuda_fp16.h>
#include <math.h>

typedef unsigned int u32;
typedef unsigned long long u64;

enum { EP_RELU = 0, EP_PLAIN = 1, EP_ADD = 2, EP_GATE = 3, EP_OUT = 4, EP_PART = 5, EP_MULG = 6 };

// ---------------- device scratch (allocation-free) ----------------
__device__ float g_xv[64 * 64 * 64 * 64];   // x voxel-major [v][64]
__device__ float g_hv[64 * 64 * 64 * 32];   // hx voxel-major (scaled 0.5)
__device__ float g_y [32 * 32 * 32 * 64];
__device__ float g_t [32 * 32 * 32 * 64];
__device__ float g_cA[32 * 32 * 32 * 64];
__device__ float g_cB[16 * 16 * 16 * 64];
__device__ float g_part[8 * 1024 * 1024];
// packed weights: per (tap, chunk16) two blobs (hi, lo) of cout*16 halves in
// exact mma.sync B-fragment order
__device__ __half g_wh  [8  * 2 * 2 * 64 * 16];
__device__ __half g_wc0 [8  * 4 * 2 * 64 * 16];
__device__ __half g_wr0 [27 * 4 * 2 * 64 * 16];
__device__ __half g_wr1 [27 * 4 * 2 * 64 * 16];
__device__ __half g_wc1 [27 * 4 * 2 * 64 * 16];
__device__ __half g_wout[27 * 4 * 2 * 32 * 16];

// ---------------- helpers ----------------
__device__ __forceinline__ u32 s2u(const void* p) {
    u32 a;
    asm("{ .reg .u64 t; cvta.to.shared.u64 t, %1; cvt.u32.u64 %0, t; }" : "=r"(a) : "l"(p));
    return a;
}
__device__ __forceinline__ u32 p2(float a, float b) {
    __half2 h = __halves2half2(__float2half_rn(a), __float2half_rn(b));
    return *reinterpret_cast<u32*>(&h);
}
__device__ __forceinline__ void ldm4(u32* r, u32 addr) {
    asm volatile("ldmatrix.sync.aligned.m8n8.x4.shared.b16 {%0,%1,%2,%3}, [%4];"
                 : "=r"(r[0]), "=r"(r[1]), "=r"(r[2]), "=r"(r[3]) : "r"(addr));
}
__device__ __forceinline__ void mma16816(float* c, const u32* a, uint2 b) {
    asm volatile(
        "mma.sync.aligned.m16n8k16.row.col.f32.f16.f16.f32 "
        "{%0,%1,%2,%3}, {%4,%5,%6,%7}, {%8,%9}, {%0,%1,%2,%3};"
        : "+f"(c[0]), "+f"(c[1]), "+f"(c[2]), "+f"(c[3])
        : "r"(a[0]), "r"(a[1]), "r"(a[2]), "r"(a[3]), "r"(b.x), "r"(b.y));
}
__device__ __forceinline__ float gatef(float a) {
    float s = 2.f * a;  // undo hx 0.5 pre-scale
    return (s > 0.f) ? 1.f / (1.f + expf(-s)) : 0.5f;
}

// ---------------- prep: relayout x (NCDHW -> [v][64]) + pack all weights ----------------
__device__ __forceinline__ void relayout_body(int blk, const float* __restrict__ in,
                                              float* __restrict__ outv, int d3) {
    __shared__ float s[64][33];
    int v0 = blk * 32;
    int t = threadIdx.x;
    int vl = t & 31;
#pragma unroll
    for (int k = 0; k < 8; ++k) {
        int c = (t >> 5) + 8 * k;
        s[c][vl] = in[(size_t)c * d3 + v0 + vl];
    }
    __syncthreads();
    int vloc = t >> 3;
#pragma unroll
    for (int k = 0; k < 2; ++k) {
        int f4 = (t & 7) * 2 + k;
        float4 w = make_float4(s[f4 * 4 + 0][vloc], s[f4 * 4 + 1][vloc],
                               s[f4 * 4 + 2][vloc], s[f4 * 4 + 3][vloc]);
        *(float4*)(outv + (size_t)(v0 + vloc) * 64 + f4 * 4) = w;
    }
}

__device__ __forceinline__ void packone(const float* __restrict__ w, __half* __restrict__ wp,
                                        int i, int cout, int cin, int taps) {
    int co = i / (cin * taps);
    int r = i % (cin * taps);
    int ci = r / taps;
    int t = r % taps;
    float v = w[i];
    float hi = __half2float(__float2half_rn(v));
    float lo = v - hi;
    int nch = cin >> 4;
    int q = ci >> 4, kk = ci & 15;
    int nf = co >> 3, nn = co & 7;
    int l = (nn << 2) + ((kk & 7) >> 1);
    int rr = kk >> 3, h = kk & 1;
    size_t base = (size_t)((t * nch + q) * 2) * (size_t)(cout * 16);
    size_t off = (size_t)nf * 128 + l * 4 + rr * 2 + h;
    wp[base + off] = __float2half_rn(hi);
    wp[base + cout * 16 + off] = __float2half_rn(lo);
}

// one launch: blocks [0, nR) relayout x ; blocks [nR, ...) pack weights
__global__ void prep(const float* __restrict__ x, float* __restrict__ xv, int d3, int nR,
                     const float* wh_, const float* wc0_, const float* wr0_,
                     const float* wr1_, const float* wc1_, const float* wout_,
                     __half* ph, __half* pc0, __half* pr0, __half* pr1,
                     __half* pc1, __half* pout) {
    if ((int)blockIdx.x < nR) {
        relayout_body(blockIdx.x, x, xv, d3);
        return;
    }
    int i = (blockIdx.x - nR) * 256 + threadIdx.x;
    const int n0 = 64 * 32 * 8;
    const int n1 = n0 + 64 * 64 * 8;
    const int n2 = n1 + 64 * 64 * 27;
    const int n3 = n2 + 64 * 64 * 27;
    const int n4 = n3 + 64 * 64 * 27;
    const int n5 = n4 + 32 * 64 * 27;
    if (i < n0)      packone(wh_,  ph,  i,      64, 32, 8);
    else if (i < n1) packone(wc0_, pc0, i - n0, 64, 64, 8);
    else if (i < n2) packone(wr0_, pr0, i - n1, 64, 64, 27);
    else if (i < n3) packone(wr1_, pr1, i - n2, 64, 64, 27);
    else if (i < n4) packone(wc1_, pc1, i - n3, 64, 64, 27);
    else if (i < n5) packone(wout_, pout, i - n4, 32, 64, 27);
}

// ---------------- tensor-core implicit conv body (2-pass: A fp16, B hi/lo) ----------------
// CTA: 256 thr = 8 warps; tile 8x4x4 = 128 voxels.
// Warp w: m-rows [32*(w&3), +32), N-half (w>>2).
// KSZ=3: register-prefetch double-buffered halo pipeline.
// EP_MULG: out0 = conv * gatef(out1[v][c])  (out1 = raw gate conv, voxel-major)
template<int KSZ, int N_, int MODE>
__device__ __forceinline__ void conv_body(
        int bt_in, int sp,
        const float* __restrict__ in, const __half* __restrict__ wp,
        float* __restrict__ out0, float* __restrict__ out1,
        int d, int cin, int taps, int nsplit, int d3) {
    constexpr int NF = N_ / 8;
    constexpr int NFH = NF / 2;
    constexpr int HN = 360;                  // halo rows (10*6*6) for 8x4x4 tile
    __shared__ __align__(16) __half ah[2][(KSZ == 3) ? HN * 16 : 8];

    const int tid = threadIdx.x, w = tid >> 5, lane = tid & 31;
    const int wm = w & 3, half_ = w >> 2;
    const int ntx = d >> 3, nty = d >> 2;
    int bt = bt_in;
    const int x0 = (bt % ntx) << 3;
    bt /= ntx;
    const int y0 = (bt % nty) << 2;
    const int z0 = (bt / nty) << 2;
    const int tpp = taps / nsplit;
    const int tap0 = sp * tpp;
    const int nch = cin >> 4;
    const int din = (KSZ == 2) ? 2 * d : d;

    float acc[2][NFH][4];
#pragma unroll
    for (int mf = 0; mf < 2; ++mf)
#pragma unroll
        for (int nf = 0; nf < NFH; ++nf)
#pragma unroll
            for (int k = 0; k < 4; ++k) acc[mf][nf][k] = 0.f;

    float4 pf[6];  // prefetch regs: ceil(1440/256)=6 per thread

    auto LOADQ = [&](int q) {
        int k = 0;
#pragma unroll
        for (int i = tid; i < HN * 4; i += 256, ++k) {
            int row = i >> 2, c4 = i & 3;
            int hx = row % 10, r2 = row / 10, hy = r2 % 6, hz = r2 / 6;
            int gx = x0 + hx - 1, gy = y0 + hy - 1, gz = z0 + hz - 1;
            float4 v = make_float4(0.f, 0.f, 0.f, 0.f);
            if ((unsigned)gx < (unsigned)d && (unsigned)gy < (unsigned)d &&
                (unsigned)gz < (unsigned)d)
                v = *(const float4*)(in + ((size_t)(gz * d + gy) * d + gx) * cin
                                     + (q << 4) + (c4 << 2));
            pf[k] = v;
        }
    };
    auto STOREQ = [&](int b) {
        int k = 0;
#pragma unroll
        for (int i = tid; i < HN * 4; i += 256, ++k) {
            int row = i >> 2, c4 = i & 3;
            float4 v = pf[k];
            uint2 hh;
            hh.x = p2(v.x, v.y); hh.y = p2(v.z, v.w);
            *(uint2*)(ah[b] + row * 16 + c4 * 4) = hh;
        }
    };

    if (KSZ == 3) {
        LOADQ(0);
        STOREQ(0);
        __syncthreads();
    }

    for (int q = 0; q < nch; ++q) {
        const int b = q & 1;
        if (KSZ == 3 && q + 1 < nch) LOADQ(q + 1);   // overlap with compute below

        const u32 ahb = s2u(ah[b]);

        for (int tt = 0; tt < tpp; ++tt) {
            const int tap = tap0 + tt;
            int dzz, dyy, dxx;
            if (KSZ == 3) { dzz = tap / 9; dyy = (tap / 3) % 3; dxx = tap % 3; }
            else          { dzz = tap >> 2; dyy = (tap >> 1) & 1; dxx = tap & 1; }

            u32 AH[2][4];
            if (KSZ == 3) {
#pragma unroll
                for (int mf = 0; mf < 2; ++mf) {
                    int r = lane & 15;
                    int mg = (wm << 5) + (mf << 4) + r;
                    int lx = mg & 7, ly = (mg >> 3) & 3, lz = mg >> 5;
                    int rowi = ((lz + dzz) * 6 + ly + dyy) * 10 + lx + dxx;
                    u32 ao = (u32)rowi * 32 + ((lane >> 4) << 4);
                    ldm4(AH[mf], ahb + ao);
                }
            } else {
#pragma unroll
                for (int mf = 0; mf < 2; ++mf) {
                    int r = lane >> 2;
                    int cb = (q << 4) + ((lane & 3) << 1);
                    int mg0 = (wm << 5) + (mf << 4) + r;
                    int mg1 = mg0 + 8;
                    int lx0 = mg0 & 7, ly0 = (mg0 >> 3) & 3, lz0 = mg0 >> 5;
                    int lx1 = mg1 & 7, ly1 = (mg1 >> 3) & 3, lz1 = mg1 >> 5;
                    size_t v0 = ((size_t)(2 * (z0 + lz0) + dzz) * din
                                 + (2 * (y0 + ly0) + dyy)) * din + 2 * (x0 + lx0) + dxx;
                    size_t v1 = ((size_t)(2 * (z0 + lz1) + dzz) * din
                                 + (2 * (y0 + ly1) + dyy)) * din + 2 * (x0 + lx1) + dxx;
                    float2 e00 = *(const float2*)(in + v0 * cin + cb);
                    float2 e10 = *(const float2*)(in + v1 * cin + cb);
                    float2 e01 = *(const float2*)(in + v0 * cin + cb + 8);
                    float2 e11 = *(const float2*)(in + v1 * cin + cb + 8);
                    AH[mf][0] = p2(e00.x, e00.y);
                    AH[mf][1] = p2(e10.x, e10.y);
                    AH[mf][2] = p2(e01.x, e01.y);
                    AH[mf][3] = p2(e11.x, e11.y);
                }
            }

            const __half* bb = wp + (size_t)((tap * nch + q) * 2) * (N_ * 16);
#pragma unroll
            for (int nf = 0; nf < NFH; ++nf) {
                const int nfg = half_ * NFH + nf;
                uint2 bh = *(const uint2*)(bb + nfg * 128 + lane * 4);
                uint2 bl = *(const uint2*)(bb + N_ * 16 + nfg * 128 + lane * 4);
                mma16816(acc[0][nf], AH[0], bh);
                mma16816(acc[1][nf], AH[1], bh);
                mma16816(acc[0][nf], AH[0], bl);
                mma16816(acc[1][nf], AH[1], bl);
            }
        }

        if (KSZ == 3 && q + 1 < nch) {
            STOREQ(b ^ 1);
            __syncthreads();
        }
    }

    // ---------------- epilogue ----------------
    const int rr = lane >> 2, cc = (lane & 3) << 1;
#pragma unroll
    for (int mf = 0; mf < 2; ++mf) {
        int mg0 = (wm << 5) + (mf << 4) + rr;
        int mg1 = mg0 + 8;
        int lx0 = mg0 & 7, ly0 = (mg0 >> 3) & 3, lz0 = mg0 >> 5;
        int lx1 = mg1 & 7, ly1 = (mg1 >> 3) & 3, lz1 = mg1 >> 5;
        size_t v0 = ((size_t)(z0 + lz0) * d + (y0 + ly0)) * d + (x0 + lx0);
        size_t v1 = ((size_t)(z0 + lz1) * d + (y0 + ly1)) * d + (x0 + lx1);
#pragma unroll
        for (int nf = 0; nf < NFH; ++nf) {
            const int nfg = half_ * NFH + nf;
            int c0 = (nfg << 3) + cc;
            float a0 = acc[mf][nf][0], a1 = acc[mf][nf][1];
            float a2 = acc[mf][nf][2], a3 = acc[mf][nf][3];
            if (MODE == EP_PART) {
                size_t slab = (size_t)sp * ((size_t)d * d * d * N_);
                *(float2*)(out0 + slab + v0 * N_ + c0) = make_float2(a0, a1);
                *(float2*)(out0 + slab + v1 * N_ + c0) = make_float2(a2, a3);
            } else if (MODE == EP_RELU || MODE == EP_PLAIN) {
                if (MODE == EP_RELU) {
                    a0 = fmaxf(a0, 0.f); a1 = fmaxf(a1, 0.f);
                    a2 = fmaxf(a2, 0.f); a3 = fmaxf(a3, 0.f);
                }
                *(float2*)(out0 + v0 * N_ + c0) = make_float2(a0, a1);
                *(float2*)(out0 + v1 * N_ + c0) = make_float2(a2, a3);
            } else if (MODE == EP_ADD) {
                float2 p0 = *(float2*)(out0 + v0 * N_ + c0);
                float2 p1 = *(float2*)(out0 + v1 * N_ + c0);
                p0.x += a0; p0.y += a1; p1.x += a2; p1.y += a3;
                *(float2*)(out0 + v0 * N_ + c0) = p0;
                *(float2*)(out0 + v1 * N_ + c0) = p1;
            } else if (MODE == EP_GATE) {
                float2 p0 = *(float2*)(out0 + v0 * N_ + c0);
                float2 p1 = *(float2*)(out0 + v1 * N_ + c0);
                p0.x *= gatef(a0); p0.y *= gatef(a1);
                p1.x *= gatef(a2); p1.y *= gatef(a3);
                *(float2*)(out0 + v0 * N_ + c0) = p0;
                *(float2*)(out0 + v1 * N_ + c0) = p1;
            } else if (MODE == EP_MULG) {
                float2 g0 = *(const float2*)(out1 + v0 * N_ + c0);
                float2 g1 = *(const float2*)(out1 + v1 * N_ + c0);
                *(float2*)(out0 + v0 * N_ + c0) =
                    make_float2(a0 * gatef(g0.x), a1 * gatef(g0.y));
                *(float2*)(out0 + v1 * N_ + c0) =
                    make_float2(a2 * gatef(g1.x), a3 * gatef(g1.y));
            } else {  // EP_OUT: channel-major 0.5x + voxel-major hx copy
                out0[(size_t)(c0 + 0) * d3 + v0] = 0.5f * a0;
                out0[(size_t)(c0 + 1) * d3 + v0] = 0.5f * a1;
                out0[(size_t)(c0 + 0) * d3 + v1] = 0.5f * a2;
                out0[(size_t)(c0 + 1) * d3 + v1] = 0.5f * a3;
                if (out1) {
                    *(float2*)(out1 + v0 * N_ + c0) = make_float2(0.5f * a0, 0.5f * a1);
                    *(float2*)(out1 + v1 * N_ + c0) = make_float2(0.5f * a2, 0.5f * a3);
                }
            }
        }
    }
}

template<int KSZ, int N_, int MODE>
__global__ __launch_bounds__(256, 2)
void convT(const float* __restrict__ in, const __half* __restrict__ wp,
           float* __restrict__ out0, float* __restrict__ out1,
           int d, int cin, int taps, int nsplit, int d3) {
    conv_body<KSZ, N_, MODE>(blockIdx.x, blockIdx.y, in, wp, out0, out1,
                             d, cin, taps, nsplit, d3);
}

// fused: conv_out@d64 (nA CTAs) + iter1 wc0@d32 (rest) — both read xv only
__global__ __launch_bounds__(256, 2)
void fused1(const float* __restrict__ xv, const __half* __restrict__ wo,
            float* __restrict__ out0, float* __restrict__ hv,
            const __half* __restrict__ wc0, float* __restrict__ bY, int nA) {
    if ((int)blockIdx.x < nA)
        conv_body<3, 32, EP_OUT>(blockIdx.x, 0, xv, wo, out0, hv,
                                 64, 64, 27, 1, 64 * 64 * 64);
    else
        conv_body<2, 64, EP_RELU>(blockIdx.x - nA, 0, xv, wc0, bY, 0,
                                  32, 64, 8, 1, 0);
}

// fused: conv_out@d32 (nA CTAs) + iter2 wc0 split (rest) — both read post-gate cA
__global__ __launch_bounds__(256, 2)
void fused2(const float* __restrict__ cA, const __half* __restrict__ wo,
            float* __restrict__ out1, float* __restrict__ hv,
            const __half* __restrict__ wc0, float* __restrict__ bP, int nA) {
    if ((int)blockIdx.x < nA)
        conv_body<3, 32, EP_OUT>(blockIdx.x, 0, cA, wo, out1, hv,
                                 32, 64, 27, 1, 32 * 32 * 32);
    else {
        int b2 = blockIdx.x - nA;          // 32 tiles x 4 splits
        conv_body<2, 64, EP_PART>(b2 & 31, b2 >> 5, cA, wc0, bP, 0,
                                  16, 64, 8, 4, 0);
    }
}

// fused: iter1 wr0 k3 (nA CTAs, bY->bT) + raw gate conv k2 (hv->bG), independent
__global__ __launch_bounds__(256, 2)
void fused3(const float* __restrict__ bY, const __half* __restrict__ wr0,
            float* __restrict__ bT,
            const float* __restrict__ hv, const __half* __restrict__ wh,
            float* __restrict__ bG, int nA) {
    if ((int)blockIdx.x < nA)
        conv_body<3, 64, EP_RELU>(blockIdx.x, 0, bY, wr0, bT, 0,
                                  32, 64, 27, 1, 0);
    else
        conv_body<2, 64, EP_PLAIN>(blockIdx.x - nA, 0, hv, wh, bG, 0,
                                   32, 32, 8, 1, 0);
}

// ---------------- split-K reduce (voxel-major) ----------------
template<int MODE>
__global__ void reduceT(const float* __restrict__ part, float* __restrict__ out0,
                        float* __restrict__ out1, int n, int slab, int nsplit,
                        int d3, int clog) {
    int i = blockIdx.x * 256 + threadIdx.x;
    if (i >= n) return;
    float s = 0.f;
    for (int k = 0; k < nsplit; ++k) s += part[(size_t)k * slab + i];
    if (MODE == EP_RELU) out0[i] = fmaxf(s, 0.f);
    else if (MODE == EP_PLAIN) out0[i] = s;
    else if (MODE == EP_ADD) out0[i] += s;
    else if (MODE == EP_GATE) out0[i] *= gatef(s);
    else {  // EP_OUT
        int c = i & ((1 << clog) - 1);
        int v = i >> clog;
        float h = 0.5f * s;
        out0[(size_t)c * d3 + v] = h;
        if (out1) out1[i] = h;
    }
}

// ---------------- driver ----------------
extern "C" void kernel_launch(void* const* d_in, const int* in_sizes, int n_in,
                              void* d_out, int out_size) {
    (void)in_sizes; (void)n_in; (void)out_size;
    const float* x     = (const float*)d_in[0];
    const float* w_h   = (const float*)d_in[1];
    const float* w_c0  = (const float*)d_in[2];
    const float* w_r0  = (const float*)d_in[3];
    const float* w_r1  = (const float*)d_in[4];
    const float* w_c1  = (const float*)d_in[5];
    const float* w_out = (const float*)d_in[6];
    float* out = (float*)d_out;

    float *xv, *hv, *bY, *bT, *cA, *cB, *bP;
    __half *wh, *wc0, *wr0, *wr1, *wc1, *wo;
    cudaGetSymbolAddress((void**)&xv, g_xv);
    cudaGetSymbolAddress((void**)&hv, g_hv);
    cudaGetSymbolAddress((void**)&bY, g_y);
    cudaGetSymbolAddress((void**)&bT, g_t);
    cudaGetSymbolAddress((void**)&cA, g_cA);
    cudaGetSymbolAddress((void**)&cB, g_cB);
    cudaGetSymbolAddress((void**)&bP, g_part);
    cudaGetSymbolAddress((void**)&wh, g_wh);
    cudaGetSymbolAddress((void**)&wc0, g_wc0);
    cudaGetSymbolAddress((void**)&wr0, g_wr0);
    cudaGetSymbolAddress((void**)&wr1, g_wr1);
    cudaGetSymbolAddress((void**)&wc1, g_wc1);
    cudaGetSymbolAddress((void**)&wo, g_wout);
    float* bPg = bP + 4 * 1024 * 1024;     // disjoint slab region for gate partials

    const int d3_64 = 262144, d3_32 = 32768, d3_16 = 4096, d3_8 = 512;

    // prep: relayout (8192 blocks) + weight pack (434 blocks) in ONE launch
    {
        const int nR = d3_64 / 32;
        const int ntot = 64 * 32 * 8 + 64 * 64 * 8 + 3 * 64 * 64 * 27 + 32 * 64 * 27;
        prep<<<nR + (ntot + 255) / 256, 256>>>(x, xv, d3_64, nR,
                                               w_h, w_c0, w_r0, w_r1, w_c1, w_out,
                                               wh, wc0, wr0, wr1, wc1, wo);
    }

    const size_t o0 = 0;
    const size_t o1 = o0 + (size_t)32 * d3_64;
    const size_t o2 = o1 + (size_t)32 * d3_32;
    const size_t o3 = o2 + (size_t)32 * d3_16;

    // fused: feas[0]=0.5*conv_out(x)@64 (+hv) || iter1 wc0 (both read xv only)
    fused1<<<2048 + 256, 256>>>(xv, wo, out + o0, hv, wc0, bY, 2048);

    // ---- iteration 1 chain: d=32 ----
    fused3<<<256 + 256, 256>>>(bY, wr0, bT, hv, wh, bP, 256);
    convT<3, 64, EP_ADD ><<<256, 256>>>(bT, wr1, bY, 0, 32, 64, 27, 1, 0);
    convT<3, 64, EP_MULG><<<256, 256>>>(bY, wc1, cA, bP, 32, 64, 27, 1, 0);

    // fused: conv_out@32 (out+o1, hv) || iter2 wc0 split (both read post-gate cA)
    fused2<<<256 + 128, 256>>>(cA, wo, out + o1, hv, wc0, bP, 256);

    // ---- iteration 2: d=16, tap-split ----
    {
        const int nv = d3_16, NB = nv / 128;
        convT<2, 64, EP_PART><<<dim3(NB, 4), 256>>>(hv, wh, bPg, 0, 16, 32, 8, 4, 0);
        reduceT<EP_RELU><<<(nv * 64 + 255) / 256, 256>>>(bP, bY, 0, nv * 64, nv * 64, 4, 0, 0);
        convT<3, 64, EP_PART><<<dim3(NB, 9), 256>>>(bY, wr0, bP, 0, 16, 64, 27, 9, 0);
        reduceT<EP_RELU><<<(nv * 64 + 255) / 256, 256>>>(bP, bT, 0, nv * 64, nv * 64, 9, 0, 0);
        convT<3, 64, EP_PART><<<dim3(NB, 9), 256>>>(bT, wr1, bP, 0, 16, 64, 27, 9, 0);
        reduceT<EP_ADD><<<(nv * 64 + 255) / 256, 256>>>(bP, bY, 0, nv * 64, nv * 64, 9, 0, 0);
        convT<3, 64, EP_PART><<<dim3(NB, 9), 256>>>(bY, wc1, bP, 0, 16, 64, 27, 9, 0);
        reduceT<EP_PLAIN><<<(nv * 64 + 255) / 256, 256>>>(bP, cB, 0, nv * 64, nv * 64, 9, 0, 0);
        reduceT<EP_GATE><<<(nv * 64 + 255) / 256, 256>>>(bPg, cB, 0, nv * 64, nv * 64, 4, 0, 0);
        convT<3, 32, EP_PART><<<dim3(NB, 9), 256>>>(cB, wo, bP, 0, 16, 64, 27, 9, 0);
        reduceT<EP_OUT><<<(nv * 32 + 255) / 256, 256>>>(bP, out + o2, hv, nv * 32, nv * 32, 9, d3_16, 5);
    }

    // ---- iteration 3: d=8, tap-split ----
    {
        const int nv = d3_8, NB = nv / 128;
        convT<2, 64, EP_PART><<<dim3(NB, 8), 256>>>(hv, wh, bPg, 0, 8, 32, 8, 8, 0);
        convT<2, 64, EP_PART><<<dim3(NB, 8), 256>>>(cB, wc0, bP, 0, 8, 64, 8, 8, 0);
        reduceT<EP_RELU><<<(nv * 64 + 255) / 256, 256>>>(bP, bY, 0, nv * 64, nv * 64, 8, 0, 0);
        convT<3, 64, EP_PART><<<dim3(NB, 27), 256>>>(bY, wr0, bP, 0, 8, 64, 27, 27, 0);
        reduceT<EP_RELU><<<(nv * 64 + 255) / 256, 256>>>(bP, bT, 0, nv * 64, nv * 64, 27, 0, 0);
        convT<3, 64, EP_PART><<<dim3(NB, 27), 256>>>(bT, wr1, bP, 0, 8, 64, 27, 27, 0);
        reduceT<EP_ADD><<<(nv * 64 + 255) / 256, 256>>>(bP, bY, 0, nv * 64, nv * 64, 27, 0, 0);
        convT<3, 64, EP_PART><<<dim3(NB, 27), 256>>>(bY, wc1, bP, 0, 8, 64, 27, 27, 0);
        reduceT<EP_PLAIN><<<(nv * 64 + 255) / 256, 256>>>(bP, cA, 0, nv * 64, nv * 64, 27, 0, 0);
        reduceT<EP_GATE><<<(nv * 64 + 255) / 256, 256>>>(bPg, cA, 0, nv * 64, nv * 64, 8, 0, 0);
        convT<3, 32, EP_PART><<<dim3(NB, 27), 256>>>(cA, wo, bP, 0, 8, 64, 27, 27, 0);
        reduceT<EP_OUT><<<(nv * 32 + 255) / 256, 256>>>(bP, out + o3, (float*)0, nv * 32, nv * 32, 27, d3_8, 5);
    }
}